// round 16
// baseline (speedup 1.0000x reference)
#include <cuda_runtime.h>

#define BB 8
#define TT 2048
#define DD 128
#define NH 4
#define QK_SCALE 0.17677669529663687f  // 1/sqrt(32)

// ---- scratch (device globals; no allocs allowed) ----
__device__ float g_q[BB * TT * DD];                 // pre-scaled Q, [b*T + t][c]
__device__ float g_k[BB * TT * DD];
__device__ float g_v[BB * TT * DD];
__device__ float g_ctx[BB * TT * DD];
__device__ float g_E[134217728];                    // exp(scores): [((b*T+q)*NH + h)*T + k], 537MB

// =====================================================================
// Kernel 1: h = hawkes@Wp^T + bp ; q = lob@Wq^T+bq (scaled); k,v from h
// =====================================================================
__device__ __forceinline__ void proj128(const float* s_in, const float* __restrict__ Wrow,
                                        float bias, float scale, float* __restrict__ outg,
                                        int row0, int rg, int c)
{
    float acc[16];
#pragma unroll
    for (int r = 0; r < 16; ++r) acc[r] = bias;
    const float4* wr = (const float4*)Wrow;
#pragma unroll 4
    for (int d4 = 0; d4 < 32; ++d4) {
        float4 wv = __ldg(wr + d4);
#pragma unroll
        for (int r = 0; r < 16; ++r) {
            float4 x = *(const float4*)&s_in[(rg * 16 + r) * 128 + 4 * d4];
            acc[r] += x.x * wv.x + x.y * wv.y + x.z * wv.z + x.w * wv.w;
        }
    }
#pragma unroll
    for (int r = 0; r < 16; ++r)
        outg[(size_t)(row0 + rg * 16 + r) * 128 + c] = acc[r] * scale;
}

__global__ __launch_bounds__(256) void qkv_kernel(
    const float* __restrict__ lob, const float* __restrict__ hawkes,
    const float* __restrict__ Wp,  const float* __restrict__ bp,
    const float* __restrict__ Win, const float* __restrict__ binp)
{
    __shared__ float s_lob[32 * 128];
    __shared__ float s_h[32 * 128];
    __shared__ float s_hawk[32 * 32];

    int tid = threadIdx.x;
    int row0 = blockIdx.x * 32;

    {   // load tiles
        const float4* lg = (const float4*)(lob + (size_t)row0 * 128);
        float4* ls = (float4*)s_lob;
        for (int i = tid; i < 1024; i += 256) ls[i] = lg[i];
        const float4* hg = (const float4*)(hawkes + (size_t)row0 * 32);
        float4* hs = (float4*)s_hawk;
        if (tid < 256) hs[tid] = hg[tid];
    }
    __syncthreads();

    int c = tid & 127, rg = tid >> 7;

    {   // h = hawkes @ Wp^T + bp  -> s_h
        float acc[16];
        float bb = bp[c];
#pragma unroll
        for (int r = 0; r < 16; ++r) acc[r] = bb;
#pragma unroll 8
        for (int j = 0; j < 32; ++j) {
            float wv = __ldg(Wp + c * 32 + j);
#pragma unroll
            for (int r = 0; r < 16; ++r) acc[r] += s_hawk[(rg * 16 + r) * 32 + j] * wv;
        }
#pragma unroll
        for (int r = 0; r < 16; ++r) s_h[(rg * 16 + r) * 128 + c] = acc[r];
    }
    __syncthreads();

    proj128(s_lob, Win + (size_t)c * 128,         binp[c],       QK_SCALE, g_q, row0, rg, c);
    proj128(s_h,   Win + (size_t)(128 + c) * 128, binp[128 + c], 1.0f,     g_k, row0, rg, c);
    proj128(s_h,   Win + (size_t)(256 + c) * 128, binp[256 + c], 1.0f,     g_v, row0, rg, c);
}

// =====================================================================
// Kernel 2: attention. Block = (b, 32-query tile), all 4 heads.
//  Phase 1: E = exp(Q K^T) -> g_E, row sums l (regs+shfl)
//  Phase 2: p = E/l, attn_w = mean_h p (direct write), ctx = P V
// =====================================================================
__global__ __launch_bounds__(256, 1) void attn_kernel(float* __restrict__ out)
{
    extern __shared__ float smem[];
    float* s_q    = smem;            // [32][128]           (phase 1)
    float* s_k    = smem + 4096;     // [128][128] swizzled (phase 1)
    float* s_v    = smem;            // [128][128]          (phase 2, overlays s_q/s_k)
    float* s_ps   = smem + 16384;    // [4][32][128]        (phase 2)
    float* s_linv = smem + 32768;    // [128]

    int tid = threadIdx.x;
    int w = tid >> 5, l = tid & 31;
    int b = blockIdx.y;
    int q0 = blockIdx.x * 32;

    const float* qg = g_q + ((size_t)b * TT + q0) * DD;
    const float* kg = g_k + (size_t)b * TT * DD;
    const float* vg = g_v + (size_t)b * TT * DD;
    float* attn = out + (size_t)BB * TT * DD + ((size_t)b * TT + q0) * TT;
    float* Eb = g_E + ((size_t)b * TT + q0) * NH * TT;

    {   // Q tile
        const float4* src = (const float4*)qg;
        float4* dst = (float4*)s_q;
        for (int i = tid; i < 1024; i += 256) dst[i] = src[i];
    }

    float lacc[4][4];
#pragma unroll
    for (int h = 0; h < 4; ++h)
#pragma unroll
        for (int qi = 0; qi < 4; ++qi) lacc[h][qi] = 0.0f;

    const int swl = l & 7;

    // ---------------- Phase 1: scores -> exp -> g_E + l ----------------
    for (int kt = 0; kt < 16; ++kt) {
        __syncthreads();
        {   // K tile, XOR-swizzled on 16B units: unit' = c4 ^ ((row>>2)&7)
            const float4* src = (const float4*)(kg + (size_t)kt * 128 * DD);
            for (int i = tid; i < 4096; i += 256) {
                int kk = i >> 5, c4 = i & 31;
                *(float4*)&s_k[kk * 128 + 4 * (c4 ^ ((kk >> 2) & 7))] = src[i];
            }
        }
        __syncthreads();

        float acc[4][4][4];
#pragma unroll
        for (int h = 0; h < 4; ++h)
#pragma unroll
            for (int qi = 0; qi < 4; ++qi)
#pragma unroll
                for (int ki = 0; ki < 4; ++ki) acc[h][qi][ki] = 0.0f;

#pragma unroll
        for (int h = 0; h < 4; ++h) {
#pragma unroll 2
            for (int dd = 0; dd < 8; ++dd) {
                int d4 = h * 8 + dd;
                float4 qv[4], kv[4];
#pragma unroll
                for (int qi = 0; qi < 4; ++qi)
                    qv[qi] = *(const float4*)&s_q[(4 * w + qi) * 128 + 4 * d4];
#pragma unroll
                for (int ki = 0; ki < 4; ++ki)
                    kv[ki] = *(const float4*)&s_k[(4 * l + ki) * 128 + 4 * (d4 ^ swl)];
#pragma unroll
                for (int qi = 0; qi < 4; ++qi)
#pragma unroll
                    for (int ki = 0; ki < 4; ++ki)
                        acc[h][qi][ki] += qv[qi].x * kv[ki].x + qv[qi].y * kv[ki].y
                                        + qv[qi].z * kv[ki].z + qv[qi].w * kv[ki].w;
            }
        }

        // exp (scores are O(1): no max-subtraction needed), store E, accumulate l
#pragma unroll
        for (int qi = 0; qi < 4; ++qi)
#pragma unroll
            for (int h = 0; h < 4; ++h) {
                float4 e;
                e.x = __expf(acc[h][qi][0]);
                e.y = __expf(acc[h][qi][1]);
                e.z = __expf(acc[h][qi][2]);
                e.w = __expf(acc[h][qi][3]);
                lacc[h][qi] += (e.x + e.y) + (e.z + e.w);
                *(float4*)(Eb + (((size_t)(4 * w + qi)) * NH + h) * TT + kt * 128 + 4 * l) = e;
            }
    }

    // reduce l across lanes (each warp owns queries 4w..4w+3 over all k)
#pragma unroll
    for (int h = 0; h < 4; ++h)
#pragma unroll
        for (int qi = 0; qi < 4; ++qi) {
            float s = lacc[h][qi];
#pragma unroll
            for (int o = 16; o; o >>= 1) s += __shfl_xor_sync(0xffffffffu, s, o);
            if (l == 0) s_linv[h * 32 + 4 * w + qi] = 1.0f / s;
        }
    __syncthreads();

    float linv[4][4];
#pragma unroll
    for (int h = 0; h < 4; ++h)
#pragma unroll
        for (int qi = 0; qi < 4; ++qi) linv[h][qi] = s_linv[h * 32 + 4 * w + qi];

    // ---------------- Phase 2: normalize, attn_w, P@V ----------------
    int qgp = tid >> 6;        // 0..3 -> owns q rows qgp*8 .. +8
    int d2  = tid & 63;        // owns dims d = 2*d2, 2*d2+1
    int h2  = d2 >> 4;         // head of those dims
    float2 ctx[8];
#pragma unroll
    for (int r = 0; r < 8; ++r) { ctx[r].x = 0.0f; ctx[r].y = 0.0f; }

    for (int kt = 0; kt < 16; ++kt) {
        __syncthreads();
        {   // V tile (no swizzle needed for our access pattern)
            const float4* src = (const float4*)(vg + (size_t)kt * 128 * DD);
            float4* dst = (float4*)s_v;
            for (int i = tid; i < 4096; i += 256) dst[i] = src[i];
        }
        // read E, normalize, write attn_w (mean over heads) + P to smem
#pragma unroll
        for (int qi = 0; qi < 4; ++qi) {
            float4 aw; aw.x = 0.0f; aw.y = 0.0f; aw.z = 0.0f; aw.w = 0.0f;
#pragma unroll
            for (int h = 0; h < 4; ++h) {
                float4 e = *(const float4*)(Eb + (((size_t)(4 * w + qi)) * NH + h) * TT + kt * 128 + 4 * l);
                float li = linv[h][qi];
                float4 p; p.x = e.x * li; p.y = e.y * li; p.z = e.z * li; p.w = e.w * li;
                aw.x += p.x; aw.y += p.y; aw.z += p.z; aw.w += p.w;
                *(float4*)&s_ps[(h * 32 + 4 * w + qi) * 128 + 4 * l] = p;
            }
            aw.x *= 0.25f; aw.y *= 0.25f; aw.z *= 0.25f; aw.w *= 0.25f;
            *(float4*)(attn + (size_t)(4 * w + qi) * TT + kt * 128 + 4 * l) = aw;
        }
        __syncthreads();

        // ctx[q][d] += sum_k P[h(d)][q][k] * V[k][d]
#pragma unroll 4
        for (int k = 0; k < 128; ++k) {
            float2 v2 = *(const float2*)&s_v[k * 128 + 2 * d2];
#pragma unroll
            for (int r = 0; r < 8; ++r) {
                float p = s_ps[(h2 * 32 + qgp * 8 + r) * 128 + k];
                ctx[r].x += p * v2.x;
                ctx[r].y += p * v2.y;
            }
        }
    }

#pragma unroll
    for (int r = 0; r < 8; ++r)
        *(float2*)(g_ctx + ((size_t)b * TT + q0 + qgp * 8 + r) * DD + 2 * d2) = ctx[r];
}

// =====================================================================
// Kernel 3: out = LayerNorm(lob + ctx @ Wo^T + bo) * gamma + beta
// =====================================================================
__global__ __launch_bounds__(256) void out_kernel(
    const float* __restrict__ lob, const float* __restrict__ Wo, const float* __restrict__ bo,
    const float* __restrict__ gamma, const float* __restrict__ beta, float* __restrict__ out)
{
    __shared__ float s_ctx[32 * 128];
    __shared__ float s_f[32 * 128];
    int tid = threadIdx.x;
    int row0 = blockIdx.x * 32;

    {
        const float4* cg = (const float4*)(g_ctx + (size_t)row0 * 128);
        float4* cs = (float4*)s_ctx;
        for (int i = tid; i < 1024; i += 256) cs[i] = cg[i];
    }
    __syncthreads();

    int c = tid & 127, rg = tid >> 7;
    {
        float acc[16];
        float bb = bo[c];
#pragma unroll
        for (int r = 0; r < 16; ++r) acc[r] = bb;
        const float4* wr = (const float4*)(Wo + (size_t)c * 128);
#pragma unroll 4
        for (int d4 = 0; d4 < 32; ++d4) {
            float4 wv = __ldg(wr + d4);
#pragma unroll
            for (int r = 0; r < 16; ++r) {
                float4 x = *(const float4*)&s_ctx[(rg * 16 + r) * 128 + 4 * d4];
                acc[r] += x.x * wv.x + x.y * wv.y + x.z * wv.z + x.w * wv.w;
            }
        }
#pragma unroll
        for (int r = 0; r < 16; ++r) {
            int row = rg * 16 + r;
            s_f[row * 128 + c] = acc[r] + lob[(size_t)(row0 + row) * 128 + c];
        }
    }
    __syncthreads();

    int w = tid >> 5, l = tid & 31;
#pragma unroll
    for (int rr = 0; rr < 4; ++rr) {
        int row = w * 4 + rr;
        float x0 = s_f[row * 128 + l];
        float x1 = s_f[row * 128 + 32 + l];
        float x2 = s_f[row * 128 + 64 + l];
        float x3 = s_f[row * 128 + 96 + l];
        float s = (x0 + x1) + (x2 + x3);
#pragma unroll
        for (int o = 16; o; o >>= 1) s += __shfl_xor_sync(0xffffffffu, s, o);
        float mu = s * (1.0f / 128.0f);
        float d0 = x0 - mu, d1 = x1 - mu, d2 = x2 - mu, d3 = x3 - mu;
        float sq = d0 * d0 + d1 * d1 + d2 * d2 + d3 * d3;
#pragma unroll
        for (int o = 16; o; o >>= 1) sq += __shfl_xor_sync(0xffffffffu, sq, o);
        float inv = rsqrtf(sq * (1.0f / 128.0f) + 1e-5f);
        size_t ob = (size_t)(row0 + row) * 128;
        out[ob + l]      = d0 * inv * gamma[l]      + beta[l];
        out[ob + 32 + l] = d1 * inv * gamma[32 + l] + beta[32 + l];
        out[ob + 64 + l] = d2 * inv * gamma[64 + l] + beta[64 + l];
        out[ob + 96 + l] = d3 * inv * gamma[96 + l] + beta[96 + l];
    }
}

// =====================================================================
extern "C" void kernel_launch(void* const* d_in, const int* in_sizes, int n_in,
                              void* d_out, int out_size)
{
    (void)in_sizes; (void)n_in; (void)out_size;
    const float* lob    = (const float*)d_in[0];
    const float* hawkes = (const float*)d_in[1];
    const float* Wp     = (const float*)d_in[2];
    const float* bp     = (const float*)d_in[3];
    const float* Win    = (const float*)d_in[4];
    const float* binp   = (const float*)d_in[5];
    const float* Wo     = (const float*)d_in[6];
    const float* bo     = (const float*)d_in[7];
    const float* gamma  = (const float*)d_in[8];
    const float* beta   = (const float*)d_in[9];
    float* out = (float*)d_out;

    const int smem_bytes = (32768 + 128) * 4;  // 131584
    cudaFuncSetAttribute(attn_kernel, cudaFuncAttributeMaxDynamicSharedMemorySize, smem_bytes);

    qkv_kernel<<<512, 256>>>(lob, hawkes, Wp, bp, Win, binp);
    attn_kernel<<<dim3(64, 8), 256, smem_bytes>>>(out);
    out_kernel<<<512, 256>>>(lob, Wo, bo, gamma, beta, out);
}